// round 1
// baseline (speedup 1.0000x reference)
#include <cuda_runtime.h>
#include <cuda_bf16.h>

#define NP      19000
#define NPAD    19456
#define E_SG    1500000
#define N_SG    800000
#define ND      1024
#define B_DD    4096
#define C       256

// ---------------- scratch (device globals; no allocation allowed) ----------
__device__ float g_hw[NP * C];      // h @ W temp
__device__ float g_h1[NP * C];
__device__ float g_h2[NP * C];
__device__ float g_dinv[NPAD];
__device__ int   g_deg[NPAD];
__device__ int   g_rowstart[NPAD + 1];
__device__ int   g_fill[NPAD];
__device__ int   g_csr_src[E_SG];
__device__ float g_drug[ND * C];
__device__ int   g_drug_start[ND + 1];

// ---------------- build CSR -----------------------------------------------
__global__ void zero_deg_kernel() {
    for (int i = blockIdx.x * blockDim.x + threadIdx.x; i < NPAD;
         i += gridDim.x * blockDim.x)
        g_deg[i] = 0;
}

__global__ void hist_kernel(const int* __restrict__ dst) {
    for (int e = blockIdx.x * blockDim.x + threadIdx.x; e < E_SG;
         e += gridDim.x * blockDim.x)
        atomicAdd(&g_deg[dst[e]], 1);
}

// single-block exclusive scan over 19000 degrees; also dinv + fill cursors
__global__ void scan_kernel() {
    __shared__ int sums[1024];
    const int CH = 19;   // 1024*19 = 19456 >= NP
    int t = threadIdx.x;
    int beg = t * CH;
    int lim = min(beg + CH, NP);
    int local = 0;
    for (int i = beg; i < lim; i++) local += g_deg[i];
    sums[t] = local;
    __syncthreads();
    if (t == 0) {
        int run = 0;
        for (int i = 0; i < 1024; i++) { int v = sums[i]; sums[i] = run; run += v; }
    }
    __syncthreads();
    int run = sums[t];
    for (int i = beg; i < lim; i++) {
        g_rowstart[i] = run;
        g_fill[i] = run;
        int d = g_deg[i];
        g_dinv[i] = rsqrtf((float)d + 1.0f);
        run += d;
    }
    if (t == 1023) g_rowstart[NP] = E_SG;
}

__global__ void csr_fill_kernel(const int* __restrict__ src,
                                const int* __restrict__ dst) {
    for (int e = blockIdx.x * blockDim.x + threadIdx.x; e < E_SG;
         e += gridDim.x * blockDim.x) {
        int pos = atomicAdd(&g_fill[dst[e]], 1);
        g_csr_src[pos] = src[e];
    }
}

// ---------------- GEMM: C[M x 256] = A[M x 256] * B[256 x 256] --------------
// BM=128 BN=64 BK=16, 256 threads, 8x4 microtile
__global__ __launch_bounds__(256) void gemm_kernel(const float* __restrict__ A,
                                                   const float* __restrict__ B,
                                                   float* __restrict__ Cout, int M) {
    __shared__ float As[16][128];
    __shared__ float Bs[16][64];
    int tid = threadIdx.x;
    int m0 = blockIdx.y * 128;
    int n0 = blockIdx.x * 64;
    int ty = tid >> 4;       // 0..15 -> rows ty*8..ty*8+7
    int tx = tid & 15;       // 0..15 -> cols tx*4..tx*4+3
    float acc[8][4] = {};

    for (int k0 = 0; k0 < 256; k0 += 16) {
        // A tile: 128x16 -> 2 float4 per thread, store transposed
        #pragma unroll
        for (int l = 0; l < 2; l++) {
            int idx = tid * 2 + l;       // 0..511
            int r   = idx >> 2;          // 0..127
            int kc  = (idx & 3) * 4;     // 0,4,8,12
            int gr  = m0 + r;
            float4 v = (gr < M) ? *(const float4*)&A[gr * 256 + k0 + kc]
                                : make_float4(0.f, 0.f, 0.f, 0.f);
            As[kc + 0][r] = v.x; As[kc + 1][r] = v.y;
            As[kc + 2][r] = v.z; As[kc + 3][r] = v.w;
        }
        // B tile: 16x64 -> 1 float4 per thread
        {
            int r = tid >> 4;            // 0..15
            int c = (tid & 15) * 4;
            *(float4*)&Bs[r][c] = *(const float4*)&B[(k0 + r) * 256 + n0 + c];
        }
        __syncthreads();
        #pragma unroll
        for (int k = 0; k < 16; k++) {
            float a[8], b[4];
            #pragma unroll
            for (int i = 0; i < 8; i++) a[i] = As[k][ty * 8 + i];
            #pragma unroll
            for (int j = 0; j < 4; j++) b[j] = Bs[k][tx * 4 + j];
            #pragma unroll
            for (int i = 0; i < 8; i++)
                #pragma unroll
                for (int j = 0; j < 4; j++)
                    acc[i][j] += a[i] * b[j];
        }
        __syncthreads();
    }
    #pragma unroll
    for (int i = 0; i < 8; i++) {
        int gr = m0 + ty * 8 + i;
        if (gr < M) {
            float4 v = make_float4(acc[i][0], acc[i][1], acc[i][2], acc[i][3]);
            *(float4*)&Cout[gr * 256 + n0 + tx * 4] = v;
        }
    }
}

// ---------------- per-row gather aggregation (no atomics) -------------------
template <bool RELU, bool RES>
__global__ __launch_bounds__(256) void agg_kernel(const float* __restrict__ hw,
                                                  const float* __restrict__ bias,
                                                  const float* __restrict__ res,
                                                  float* __restrict__ out) {
    int i   = blockIdx.x;
    int col = threadIdx.x;
    int beg = g_rowstart[i];
    int end = g_rowstart[i + 1];
    __shared__ int   s_src[256];
    __shared__ float s_w[256];
    float a0 = 0.f, a1 = 0.f, a2 = 0.f, a3 = 0.f;

    for (int base = beg; base < end; base += 256) {
        int n = min(256, end - base);
        if (col < n) {
            int s = g_csr_src[base + col];
            s_src[col] = s * 256;
            s_w[col]   = g_dinv[s];
        }
        __syncthreads();
        int j = 0;
        for (; j + 4 <= n; j += 4) {
            a0 += hw[s_src[j + 0] + col] * s_w[j + 0];
            a1 += hw[s_src[j + 1] + col] * s_w[j + 1];
            a2 += hw[s_src[j + 2] + col] * s_w[j + 2];
            a3 += hw[s_src[j + 3] + col] * s_w[j + 3];
        }
        for (; j < n; j++) a0 += hw[s_src[j] + col] * s_w[j];
        __syncthreads();
    }
    float di   = g_dinv[i];
    float self = hw[i * 256 + col];
    float v = di * ((a0 + a1 + a2 + a3) + self * di) + bias[col];
    if (RES) v += res[i * 256 + col];
    if (RELU) v = fmaxf(v, 0.f);
    out[i * 256 + col] = v;
}

// ---------------- pooling ---------------------------------------------------
__global__ void bounds_kernel(const int* __restrict__ idx) {
    int d = blockIdx.x * blockDim.x + threadIdx.x;
    if (d > ND) return;
    if (d == ND) { g_drug_start[ND] = N_SG; return; }
    int lo = 0, hi = N_SG;
    while (lo < hi) {
        int mid = (lo + hi) >> 1;
        if (idx[mid] < d) lo = mid + 1; else hi = mid;
    }
    g_drug_start[d] = lo;
}

__global__ __launch_bounds__(256) void pool_kernel(const int* __restrict__ nodes,
                                                   const float* __restrict__ h2) {
    int d   = blockIdx.x;
    int col = threadIdx.x;
    int beg = g_drug_start[d];
    int end = g_drug_start[d + 1];
    __shared__ int s_n[256];
    float a0 = 0.f, a1 = 0.f, a2 = 0.f, a3 = 0.f;

    for (int base = beg; base < end; base += 256) {
        int n = min(256, end - base);
        if (col < n) s_n[col] = nodes[base + col] * 256;
        __syncthreads();
        int j = 0;
        for (; j + 4 <= n; j += 4) {
            a0 += h2[s_n[j + 0] + col];
            a1 += h2[s_n[j + 1] + col];
            a2 += h2[s_n[j + 2] + col];
            a3 += h2[s_n[j + 3] + col];
        }
        for (; j < n; j++) a0 += h2[s_n[j] + col];
        __syncthreads();
    }
    float cnt = (float)(end - beg);
    g_drug[d * 256 + col] = (a0 + a1 + a2 + a3) / fmaxf(cnt, 1.0f);
}

// ---------------- prediction head ------------------------------------------
__global__ void head_kernel(const int* __restrict__ ddb, float* __restrict__ out) {
    int gw   = (blockIdx.x * blockDim.x + threadIdx.x) >> 5;
    int lane = threadIdx.x & 31;
    if (gw >= B_DD) return;
    int a = ddb[gw];
    int b = ddb[B_DD + gw];
    float s = 0.f;
    #pragma unroll
    for (int c = lane; c < 256; c += 32)
        s += g_drug[a * 256 + c] * g_drug[b * 256 + c];
    #pragma unroll
    for (int off = 16; off; off >>= 1)
        s += __shfl_down_sync(0xffffffffu, s, off);
    if (lane == 0) out[gw] = s;
}

// ---------------- launch ----------------------------------------------------
extern "C" void kernel_launch(void* const* d_in, const int* in_sizes, int n_in,
                              void* d_out, int out_size) {
    const float* x     = (const float*)d_in[0];    // [19000,256]
    const int*   ddb   = (const int*)d_in[1];      // [2,4096]
    const int*   sg_ei = (const int*)d_in[4];      // [2,1.5M]
    const int*   nodes = (const int*)d_in[5];      // [800k]
    const int*   avgix = (const int*)d_in[6];      // [800k] sorted
    const float* W1    = (const float*)d_in[7];
    const float* b1    = (const float*)d_in[8];
    const float* W2    = (const float*)d_in[9];
    const float* b2    = (const float*)d_in[10];
    float* out = (float*)d_out;

    const int* src = sg_ei;
    const int* dst = sg_ei + E_SG;

    zero_deg_kernel<<<76, 256>>>();
    hist_kernel<<<2048, 256>>>(dst);
    scan_kernel<<<1, 1024>>>();
    csr_fill_kernel<<<2048, 256>>>(src, dst);

    dim3 ggrid(4, 149);   // (256/64) x ceil(19000/128)
    gemm_kernel<<<ggrid, 256>>>(x, W1, g_hw, NP);
    agg_kernel<true, false><<<NP, 256>>>(g_hw, b1, nullptr, g_h1);

    gemm_kernel<<<ggrid, 256>>>(g_h1, W2, g_hw, NP);
    agg_kernel<false, true><<<NP, 256>>>(g_hw, b2, g_h1, g_h2);

    bounds_kernel<<<5, 256>>>(avgix);
    pool_kernel<<<ND, 256>>>(nodes, g_h2);
    head_kernel<<<(B_DD * 32 + 255) / 256, 256>>>(ddb, out);
}

// round 3
// speedup vs baseline: 1.1391x; 1.1391x over previous
#include <cuda_runtime.h>
#include <cuda_bf16.h>

#define NP      19000
#define NPAD    19456
#define E_SG    1500000
#define N_SG    800000
#define ND      1024
#define B_DD    4096
#define C       256
#define C4      64          // C / 4

// ---------------- scratch (device globals; no allocation allowed) ----------
__device__ float4 g_hw[NP * C4];
__device__ float4 g_h1[NP * C4];
__device__ float4 g_h2[NP * C4];
__device__ float  g_dinv[NPAD];
__device__ int    g_deg[NPAD];
__device__ int    g_rowstart[NPAD + 1];
__device__ int    g_fill[NPAD];
__device__ int    g_csr_src[E_SG];
__device__ float4 g_drug[ND * C4];
__device__ int    g_drug_start[ND + 1];

// ---------------- build CSR -----------------------------------------------
__global__ void zero_deg_kernel() {
    for (int i = blockIdx.x * blockDim.x + threadIdx.x; i < NPAD;
         i += gridDim.x * blockDim.x)
        g_deg[i] = 0;
}

__global__ void hist_kernel(const int* __restrict__ dst) {
    for (int e = blockIdx.x * blockDim.x + threadIdx.x; e < E_SG;
         e += gridDim.x * blockDim.x)
        atomicAdd(&g_deg[dst[e]], 1);
}

// single-block scan over degrees; also dinv + fill cursors + drug bounds
__global__ void scan_kernel(const int* __restrict__ avgix) {
    __shared__ int sums[1024];
    const int CH = 19;   // 1024*19 = 19456 >= NP
    int t = threadIdx.x;
    int beg = t * CH;
    int lim = min(beg + CH, NP);
    int local = 0;
    for (int i = beg; i < lim; i++) local += g_deg[i];
    sums[t] = local;
    __syncthreads();
    if (t == 0) {
        int run = 0;
        for (int i = 0; i < 1024; i++) { int v = sums[i]; sums[i] = run; run += v; }
    }
    __syncthreads();
    int run = sums[t];
    for (int i = beg; i < lim; i++) {
        g_rowstart[i] = run;
        g_fill[i] = run;
        int d = g_deg[i];
        g_dinv[i] = rsqrtf((float)d + 1.0f);
        run += d;
    }
    if (t == 1023) g_rowstart[NP] = E_SG;

    // fused drug-boundary binary search (1025 bounds over 1024 threads)
    for (int d = t; d <= ND; d += 1024) {
        if (d == ND) { g_drug_start[ND] = N_SG; continue; }
        int lo = 0, hi = N_SG;
        while (lo < hi) {
            int mid = (lo + hi) >> 1;
            if (avgix[mid] < d) lo = mid + 1; else hi = mid;
        }
        g_drug_start[d] = lo;
    }
}

__global__ void csr_fill_kernel(const int* __restrict__ src,
                                const int* __restrict__ dst) {
    for (int e = blockIdx.x * blockDim.x + threadIdx.x; e < E_SG;
         e += gridDim.x * blockDim.x) {
        int pos = atomicAdd(&g_fill[dst[e]], 1);
        g_csr_src[pos] = src[e];
    }
}

// ---------------- GEMM: C[M x 256] = A[M x 256] * B[256 x 256] --------------
__global__ __launch_bounds__(256) void gemm_kernel(const float* __restrict__ A,
                                                   const float* __restrict__ B,
                                                   float* __restrict__ Cout, int M) {
    __shared__ float As[16][128];
    __shared__ float Bs[16][64];
    int tid = threadIdx.x;
    int m0 = blockIdx.y * 128;
    int n0 = blockIdx.x * 64;
    int ty = tid >> 4;
    int tx = tid & 15;
    float acc[8][4] = {};

    for (int k0 = 0; k0 < 256; k0 += 16) {
        #pragma unroll
        for (int l = 0; l < 2; l++) {
            int idx = tid * 2 + l;
            int r   = idx >> 2;
            int kc  = (idx & 3) * 4;
            int gr  = m0 + r;
            float4 v = (gr < M) ? *(const float4*)&A[gr * 256 + k0 + kc]
                                : make_float4(0.f, 0.f, 0.f, 0.f);
            As[kc + 0][r] = v.x; As[kc + 1][r] = v.y;
            As[kc + 2][r] = v.z; As[kc + 3][r] = v.w;
        }
        {
            int r = tid >> 4;
            int c = (tid & 15) * 4;
            *(float4*)&Bs[r][c] = *(const float4*)&B[(k0 + r) * 256 + n0 + c];
        }
        __syncthreads();
        #pragma unroll
        for (int k = 0; k < 16; k++) {
            float a[8], b[4];
            #pragma unroll
            for (int i = 0; i < 8; i++) a[i] = As[k][ty * 8 + i];
            #pragma unroll
            for (int j = 0; j < 4; j++) b[j] = Bs[k][tx * 4 + j];
            #pragma unroll
            for (int i = 0; i < 8; i++)
                #pragma unroll
                for (int j = 0; j < 4; j++)
                    acc[i][j] += a[i] * b[j];
        }
        __syncthreads();
    }
    #pragma unroll
    for (int i = 0; i < 8; i++) {
        int gr = m0 + ty * 8 + i;
        if (gr < M) {
            float4 v = make_float4(acc[i][0], acc[i][1], acc[i][2], acc[i][3]);
            *(float4*)&Cout[gr * 256 + n0 + tx * 4] = v;
        }
    }
}

// ---------------- per-row gather aggregation (float4, 4 edge groups) --------
template <bool RELU, bool RES>
__global__ __launch_bounds__(256) void agg_kernel(const float4* __restrict__ hw,
                                                  const float4* __restrict__ bias,
                                                  const float4* __restrict__ res,
                                                  float4* __restrict__ out) {
    int i      = blockIdx.x;
    int lane64 = threadIdx.x & 63;   // column block (4 cols each)
    int grp    = threadIdx.x >> 6;   // edge group 0..3
    int beg = g_rowstart[i];
    int end = g_rowstart[i + 1];
    __shared__ int    s_src[256];
    __shared__ float  s_w[256];
    __shared__ float4 s_red[256];
    float4 acc = make_float4(0.f, 0.f, 0.f, 0.f);

    for (int base = beg; base < end; base += 256) {
        int n = min(256, end - base);
        int t = threadIdx.x;
        if (t < n) {
            int s = g_csr_src[base + t];
            s_src[t] = s * C4;
            s_w[t]   = g_dinv[s];
        }
        __syncthreads();
        int j = grp;
        for (; j + 8 <= n; j += 8) {
            int   r0 = s_src[j],     r1 = s_src[j + 4];
            float w0 = s_w[j],       w1 = s_w[j + 4];
            float4 v0 = hw[r0 + lane64];
            float4 v1 = hw[r1 + lane64];
            acc.x += v0.x * w0; acc.y += v0.y * w0;
            acc.z += v0.z * w0; acc.w += v0.w * w0;
            acc.x += v1.x * w1; acc.y += v1.y * w1;
            acc.z += v1.z * w1; acc.w += v1.w * w1;
        }
        for (; j < n; j += 4) {
            int   r = s_src[j];
            float w = s_w[j];
            float4 v = hw[r + lane64];
            acc.x += v.x * w; acc.y += v.y * w;
            acc.z += v.z * w; acc.w += v.w * w;
        }
        __syncthreads();
    }
    s_red[threadIdx.x] = acc;
    __syncthreads();
    if (threadIdx.x < 64) {
        float4 a = s_red[lane64];
        float4 b = s_red[lane64 + 64];
        float4 c = s_red[lane64 + 128];
        float4 d = s_red[lane64 + 192];
        float sx = a.x + b.x + c.x + d.x;
        float sy = a.y + b.y + c.y + d.y;
        float sz = a.z + b.z + c.z + d.z;
        float sw = a.w + b.w + c.w + d.w;
        float  di   = g_dinv[i];
        float4 self = hw[i * C4 + lane64];
        float4 bi   = bias[lane64];
        float4 v;
        v.x = di * (sx + self.x * di) + bi.x;
        v.y = di * (sy + self.y * di) + bi.y;
        v.z = di * (sz + self.z * di) + bi.z;
        v.w = di * (sw + self.w * di) + bi.w;
        if (RES) {
            float4 r4 = res[i * C4 + lane64];
            v.x += r4.x; v.y += r4.y; v.z += r4.z; v.w += r4.w;
        }
        if (RELU) {
            v.x = fmaxf(v.x, 0.f); v.y = fmaxf(v.y, 0.f);
            v.z = fmaxf(v.z, 0.f); v.w = fmaxf(v.w, 0.f);
        }
        out[i * C4 + lane64] = v;
    }
}

// ---------------- pooling (float4, 4 node groups) ---------------------------
__global__ __launch_bounds__(256) void pool_kernel(const int* __restrict__ nodes,
                                                   const float4* __restrict__ h2) {
    int d      = blockIdx.x;
    int lane64 = threadIdx.x & 63;
    int grp    = threadIdx.x >> 6;
    int beg = g_drug_start[d];
    int end = g_drug_start[d + 1];
    __shared__ int    s_n[256];
    __shared__ float4 s_red[256];
    float4 acc = make_float4(0.f, 0.f, 0.f, 0.f);

    for (int base = beg; base < end; base += 256) {
        int n = min(256, end - base);
        int t = threadIdx.x;
        if (t < n) s_n[t] = nodes[base + t] * C4;
        __syncthreads();
        int j = grp;
        for (; j + 8 <= n; j += 8) {
            float4 v0 = h2[s_n[j]     + lane64];
            float4 v1 = h2[s_n[j + 4] + lane64];
            acc.x += v0.x + v1.x; acc.y += v0.y + v1.y;
            acc.z += v0.z + v1.z; acc.w += v0.w + v1.w;
        }
        for (; j < n; j += 4) {
            float4 v = h2[s_n[j] + lane64];
            acc.x += v.x; acc.y += v.y; acc.z += v.z; acc.w += v.w;
        }
        __syncthreads();
    }
    s_red[threadIdx.x] = acc;
    __syncthreads();
    if (threadIdx.x < 64) {
        float4 a = s_red[lane64];
        float4 b = s_red[lane64 + 64];
        float4 c = s_red[lane64 + 128];
        float4 e = s_red[lane64 + 192];
        float inv = 1.0f / fmaxf((float)(end - beg), 1.0f);
        float4 v;
        v.x = (a.x + b.x + c.x + e.x) * inv;
        v.y = (a.y + b.y + c.y + e.y) * inv;
        v.z = (a.z + b.z + c.z + e.z) * inv;
        v.w = (a.w + b.w + c.w + e.w) * inv;
        g_drug[d * C4 + lane64] = v;
    }
}

// ---------------- prediction head ------------------------------------------
__global__ void head_kernel(const int* __restrict__ ddb, float* __restrict__ out) {
    int gw   = (blockIdx.x * blockDim.x + threadIdx.x) >> 5;
    int lane = threadIdx.x & 31;
    if (gw >= B_DD) return;
    int a = ddb[gw];
    int b = ddb[B_DD + gw];
    float s = 0.f;
    #pragma unroll
    for (int c = lane; c < C4; c += 32) {
        float4 va = g_drug[a * C4 + c];
        float4 vb = g_drug[b * C4 + c];
        s += va.x * vb.x + va.y * vb.y + va.z * vb.z + va.w * vb.w;
    }
    #pragma unroll
    for (int off = 16; off; off >>= 1)
        s += __shfl_down_sync(0xffffffffu, s, off);
    if (lane == 0) out[gw] = s;
}

// ---------------- launch ----------------------------------------------------
extern "C" void kernel_launch(void* const* d_in, const int* in_sizes, int n_in,
                              void* d_out, int out_size) {
    const float* x     = (const float*)d_in[0];
    const int*   ddb   = (const int*)d_in[1];
    const int*   sg_ei = (const int*)d_in[4];
    const int*   nodes = (const int*)d_in[5];
    const int*   avgix = (const int*)d_in[6];
    const float* W1    = (const float*)d_in[7];
    const float* b1    = (const float*)d_in[8];
    const float* W2    = (const float*)d_in[9];
    const float* b2    = (const float*)d_in[10];
    float* out = (float*)d_out;

    const int* src = sg_ei;
    const int* dst = sg_ei + E_SG;

    zero_deg_kernel<<<76, 256>>>();
    hist_kernel<<<2048, 256>>>(dst);
    scan_kernel<<<1, 1024>>>(avgix);
    csr_fill_kernel<<<2048, 256>>>(src, dst);

    dim3 ggrid(4, 149);
    gemm_kernel<<<ggrid, 256>>>(x, W1, (float*)g_hw, NP);
    agg_kernel<true, false><<<NP, 256>>>(g_hw, (const float4*)b1, nullptr, g_h1);

    gemm_kernel<<<ggrid, 256>>>((const float*)g_h1, W2, (float*)g_hw, NP);
    agg_kernel<false, true><<<NP, 256>>>(g_hw, (const float4*)b2, g_h1, g_h2);

    pool_kernel<<<ND, 256>>>(nodes, g_h2);
    head_kernel<<<(B_DD * 32 + 255) / 256, 256>>>(ddb, out);
}

// round 4
// speedup vs baseline: 27.4262x; 24.0777x over previous
#include <cuda_runtime.h>

#define NP     19000
#define E_SG   1500000
#define N_SG   800000
#define ND     1024
#define B_DD   4096
#define NB     148
#define NT     256
#define CHUNK  129          // ceil(NP/NB) = 129 ; 148*129 = 19092 >= 19000
#define ASTR   264          // A tile row stride (floats), 256 + 8 pad
#define NTILE  297          // ceil(19000/64)

// ---------------- persistent device state (no allocation allowed) -----------
__device__ float    g_h1[NP * 256];
__device__ float    g_h2[NP * 256];
__device__ float    g_dinv[NP];
__device__ int      g_deg[NP];           // must be zero at kernel entry; re-zeroed in csr phase
__device__ int      g_rowstart[NP + 1];
__device__ int      g_fill[NP];
__device__ int      g_csr_src[E_SG];
__device__ float    g_drug[ND * 256];
__device__ int      g_drug_start[ND + 1];
__device__ int      g_part[NB];
__device__ int      g_poff[NB];
__device__ unsigned g_cnt;               // barrier arrival counter (self-resetting)
__device__ unsigned g_gen;               // barrier generation (monotone forever)

// Software grid barrier. Safe because all 148 blocks are co-resident
// (grid == 148 <= SM count; 84KB smem, ~110 regs -> >=1 block/SM trivially).
// g_gen is never reset: each run snapshots gen0 at entry (before any arrival
// can complete, since completion needs all 148 blocks started).
__device__ __forceinline__ void gridbar(unsigned gen0, unsigned k) {
    __syncthreads();
    if (threadIdx.x == 0) {
        __threadfence();
        unsigned pos = atomicAdd(&g_cnt, 1u);
        if (pos == NB - 1u) {
            atomicExch(&g_cnt, 0u);
            __threadfence();
            atomicAdd(&g_gen, 1u);
        } else {
            unsigned target = gen0 + k;
            while ((int)(*(volatile unsigned*)&g_gen - target) < 0) __nanosleep(64);
        }
        __threadfence();
    }
    __syncthreads();
}

// ---------------- fused GCN layer: agg (warp-per-row) + GEMM in smem --------
__device__ void layer_phase(const float4* __restrict__ in, const float* __restrict__ W,
                            const float* __restrict__ bias, const float4* __restrict__ resid,
                            float4* __restrict__ out, bool relu,
                            float* A, float* Bs) {
    const int tid  = threadIdx.x;
    const int lane = tid & 31;
    const int wid  = tid >> 5;           // 0..7

    for (int tile = blockIdx.x; tile < NTILE; tile += NB) {
        const int r0 = tile * 64;
        // ---- gather phase: warp wid produces rows wid*8 .. wid*8+7 ----
        for (int i = 0; i < 8; i++) {
            int rr = wid * 8 + i;
            int r  = r0 + rr;
            float4 a0 = make_float4(0.f, 0.f, 0.f, 0.f);
            float4 a1 = make_float4(0.f, 0.f, 0.f, 0.f);
            if (r < NP) {
                int beg = g_rowstart[r];
                int end = g_rowstart[r + 1];
                for (int base = beg; base < end; base += 32) {
                    int m = min(32, end - base);
                    int sidx = 0; float sw = 0.f;
                    if (lane < m) {
                        int s = g_csr_src[base + lane];
                        sidx = s * 64;
                        sw   = g_dinv[s];
                    }
                    for (int k = 0; k < m; k++) {
                        int   idx = __shfl_sync(0xffffffffu, sidx, k);
                        float w   = __shfl_sync(0xffffffffu, sw,   k);
                        float4 v0 = in[idx + lane * 2];
                        float4 v1 = in[idx + lane * 2 + 1];
                        a0.x = fmaf(v0.x, w, a0.x); a0.y = fmaf(v0.y, w, a0.y);
                        a0.z = fmaf(v0.z, w, a0.z); a0.w = fmaf(v0.w, w, a0.w);
                        a1.x = fmaf(v1.x, w, a1.x); a1.y = fmaf(v1.y, w, a1.y);
                        a1.z = fmaf(v1.z, w, a1.z); a1.w = fmaf(v1.w, w, a1.w);
                    }
                }
                float di = g_dinv[r];
                float4 s0 = in[r * 64 + lane * 2];
                float4 s1 = in[r * 64 + lane * 2 + 1];
                a0.x = (a0.x + s0.x * di) * di; a0.y = (a0.y + s0.y * di) * di;
                a0.z = (a0.z + s0.z * di) * di; a0.w = (a0.w + s0.w * di) * di;
                a1.x = (a1.x + s1.x * di) * di; a1.y = (a1.y + s1.y * di) * di;
                a1.z = (a1.z + s1.z * di) * di; a1.w = (a1.w + s1.w * di) * di;
            }
            float* Ar = A + rr * ASTR + lane * 8;
            *(float4*)(Ar)     = a0;
            *(float4*)(Ar + 4) = a1;
        }
        __syncthreads();

        // ---- GEMM phase: H[64,256] = A[64,256] * W[256,256] ----
        const int rowg = wid;            // warp-uniform -> broadcast LDS for a[]
        const int colg = lane;           // cols colg*8 .. +7
        float acc[8][8];
        #pragma unroll
        for (int i = 0; i < 8; i++)
            #pragma unroll
            for (int j = 0; j < 8; j++) acc[i][j] = 0.f;

        for (int k0 = 0; k0 < 256; k0 += 16) {
            #pragma unroll
            for (int q = 0; q < 4; q++) {
                int l  = tid + 256 * q;      // 0..1023
                int br = l >> 6;             // 0..15
                int bc = (l & 63) * 4;       // 0..252
                *(float4*)&Bs[br * 256 + bc] = *(const float4*)&W[(k0 + br) * 256 + bc];
            }
            __syncthreads();
            #pragma unroll
            for (int k = 0; k < 16; k++) {
                float a[8];
                #pragma unroll
                for (int i = 0; i < 8; i++) a[i] = A[(rowg * 8 + i) * ASTR + k0 + k];
                float4 b0 = *(float4*)&Bs[k * 256 + colg * 8];
                float4 b1 = *(float4*)&Bs[k * 256 + colg * 8 + 4];
                #pragma unroll
                for (int i = 0; i < 8; i++) {
                    acc[i][0] = fmaf(a[i], b0.x, acc[i][0]);
                    acc[i][1] = fmaf(a[i], b0.y, acc[i][1]);
                    acc[i][2] = fmaf(a[i], b0.z, acc[i][2]);
                    acc[i][3] = fmaf(a[i], b0.w, acc[i][3]);
                    acc[i][4] = fmaf(a[i], b1.x, acc[i][4]);
                    acc[i][5] = fmaf(a[i], b1.y, acc[i][5]);
                    acc[i][6] = fmaf(a[i], b1.z, acc[i][6]);
                    acc[i][7] = fmaf(a[i], b1.w, acc[i][7]);
                }
            }
            __syncthreads();
        }

        // ---- epilogue: bias (+residual) (+relu) -> out ----
        float4 bi0 = *(const float4*)&bias[colg * 8];
        float4 bi1 = *(const float4*)&bias[colg * 8 + 4];
        #pragma unroll
        for (int i = 0; i < 8; i++) {
            int r = r0 + rowg * 8 + i;
            if (r < NP) {
                float4 o0 = make_float4(acc[i][0] + bi0.x, acc[i][1] + bi0.y,
                                        acc[i][2] + bi0.z, acc[i][3] + bi0.w);
                float4 o1 = make_float4(acc[i][4] + bi1.x, acc[i][5] + bi1.y,
                                        acc[i][6] + bi1.z, acc[i][7] + bi1.w);
                if (resid) {
                    float4 r4 = resid[r * 64 + colg * 2];
                    float4 r5 = resid[r * 64 + colg * 2 + 1];
                    o0.x += r4.x; o0.y += r4.y; o0.z += r4.z; o0.w += r4.w;
                    o1.x += r5.x; o1.y += r5.y; o1.z += r5.z; o1.w += r5.w;
                }
                if (relu) {
                    o0.x = fmaxf(o0.x, 0.f); o0.y = fmaxf(o0.y, 0.f);
                    o0.z = fmaxf(o0.z, 0.f); o0.w = fmaxf(o0.w, 0.f);
                    o1.x = fmaxf(o1.x, 0.f); o1.y = fmaxf(o1.y, 0.f);
                    o1.z = fmaxf(o1.z, 0.f); o1.w = fmaxf(o1.w, 0.f);
                }
                out[r * 64 + colg * 2]     = o0;
                out[r * 64 + colg * 2 + 1] = o1;
            }
        }
        __syncthreads();
    }
}

// ---------------- the single mega-kernel ------------------------------------
__global__ __launch_bounds__(NT) void mega_kernel(
    const float* __restrict__ x, const int* __restrict__ ddb,
    const int* __restrict__ src, const int* __restrict__ dst,
    const int* __restrict__ nodes, const int* __restrict__ avgix,
    const float* __restrict__ W1, const float* __restrict__ b1,
    const float* __restrict__ W2, const float* __restrict__ b2,
    float* __restrict__ out)
{
    extern __shared__ float smem[];
    float* A  = smem;                  // 64 * 264 floats
    float* Bs = smem + 64 * ASTR;      // 16 * 256 floats
    __shared__ unsigned s_gen0;

    const int tid  = threadIdx.x;
    const int lane = tid & 31;
    const int wid  = tid >> 5;
    const int gtid = blockIdx.x * NT + tid;
    const int gs   = NB * NT;

    if (tid == 0) s_gen0 = *(volatile unsigned*)&g_gen;
    __syncthreads();
    const unsigned gen0 = s_gen0;

    // ---- P0: degree histogram + drug boundary binary search ----
    for (int e = gtid; e < E_SG; e += gs)
        atomicAdd(&g_deg[dst[e]], 1);
    if (gtid <= ND) {
        if (gtid == ND) g_drug_start[ND] = N_SG;
        else {
            int lo = 0, hi = N_SG;
            while (lo < hi) {
                int mid = (lo + hi) >> 1;
                if (avgix[mid] < gtid) lo = mid + 1; else hi = mid;
            }
            g_drug_start[gtid] = lo;
        }
    }
    gridbar(gen0, 1);

    // ---- P1a: per-block chunk sums ----
    int* si = (int*)A;
    {
        int n0  = blockIdx.x * CHUNK;
        int len = NP - n0; if (len > CHUNK) len = CHUNK; if (len < 0) len = 0;
        int v = (tid < len) ? g_deg[n0 + tid] : 0;
        si[tid] = v;
        __syncthreads();
        if (tid == 0) {
            int s = 0;
            for (int i = 0; i < len; i++) s += si[i];
            g_part[blockIdx.x] = s;
        }
    }
    gridbar(gen0, 2);

    // ---- P1b: block 0 scans the 148 partials ----
    if (blockIdx.x == 0) {
        int pv = (tid < NB) ? g_part[tid] : 0;
        si[tid] = pv;
        __syncthreads();
        if (tid == 0) {
            int run = 0;
            for (int i = 0; i < NB; i++) { int t = si[i]; si[i] = run; run += t; }
        }
        __syncthreads();
        if (tid < NB) g_poff[tid] = si[tid];
    }
    gridbar(gen0, 3);

    // ---- P1c: per-chunk prefix -> rowstart/fill/dinv ----
    {
        int n0  = blockIdx.x * CHUNK;
        int len = NP - n0; if (len > CHUNK) len = CHUNK; if (len < 0) len = 0;
        int v = (tid < len) ? g_deg[n0 + tid] : 0;
        si[tid] = v;
        __syncthreads();
        if (tid == 0) {
            int run = g_poff[blockIdx.x];
            for (int i = 0; i < len; i++) { int t = si[i]; si[i] = run; run += t; }
        }
        __syncthreads();
        if (tid < len) {
            int node = n0 + tid;
            int rs = si[tid];
            g_rowstart[node] = rs;
            g_fill[node]     = rs;
            g_dinv[node]     = rsqrtf((float)v + 1.0f);
        }
        if (blockIdx.x == 0 && tid == 0) g_rowstart[NP] = E_SG;
    }
    gridbar(gen0, 4);

    // ---- P2: CSR fill + reset g_deg for next replay ----
    for (int e = gtid; e < E_SG; e += gs) {
        int d   = dst[e];
        int pos = atomicAdd(&g_fill[d], 1);
        g_csr_src[pos] = src[e];
    }
    for (int i = gtid; i < NP; i += gs) g_deg[i] = 0;
    gridbar(gen0, 5);

    // ---- P3: layer 1  h1 = relu(agg(x) @ W1 + b1) ----
    layer_phase((const float4*)x, W1, b1, nullptr, (float4*)g_h1, true, A, Bs);
    gridbar(gen0, 6);

    // ---- P4: layer 2  h2 = agg(h1) @ W2 + b2 + h1 ----
    layer_phase((const float4*)g_h1, W2, b2, (const float4*)g_h1, (float4*)g_h2, false, A, Bs);
    gridbar(gen0, 7);

    // ---- P5: scatter-mean pooling (warp gather, smem reduce) ----
    {
        const float4* h2 = (const float4*)g_h2;
        for (int d = blockIdx.x; d < ND; d += NB) {
            int beg = g_drug_start[d];
            int end = g_drug_start[d + 1];
            float4 a0 = make_float4(0.f, 0.f, 0.f, 0.f);
            float4 a1 = make_float4(0.f, 0.f, 0.f, 0.f);
            for (int base = beg + wid * 32; base < end; base += 256) {
                int m = min(32, end - base);
                int nidx = 0;
                if (lane < m) nidx = nodes[base + lane] * 64;
                for (int k = 0; k < m; k++) {
                    int idx = __shfl_sync(0xffffffffu, nidx, k);
                    float4 v0 = h2[idx + lane * 2];
                    float4 v1 = h2[idx + lane * 2 + 1];
                    a0.x += v0.x; a0.y += v0.y; a0.z += v0.z; a0.w += v0.w;
                    a1.x += v1.x; a1.y += v1.y; a1.z += v1.z; a1.w += v1.w;
                }
            }
            __syncthreads();
            float* P = A;   // 8 warps x 256 floats
            *(float4*)&P[wid * 256 + lane * 8]     = a0;
            *(float4*)&P[wid * 256 + lane * 8 + 4] = a1;
            __syncthreads();
            float s = 0.f;
            #pragma unroll
            for (int w = 0; w < 8; w++) s += P[w * 256 + tid];
            float inv = 1.0f / fmaxf((float)(end - beg), 1.0f);
            g_drug[d * 256 + tid] = s * inv;
        }
    }
    gridbar(gen0, 8);

    // ---- P6: prediction head ----
    {
        const float4* gd = (const float4*)g_drug;
        for (int p = blockIdx.x * 8 + wid; p < B_DD; p += NB * 8) {
            int a = ddb[p];
            int b = ddb[B_DD + p];
            float4 va0 = gd[a * 64 + lane * 2], va1 = gd[a * 64 + lane * 2 + 1];
            float4 vb0 = gd[b * 64 + lane * 2], vb1 = gd[b * 64 + lane * 2 + 1];
            float s = va0.x * vb0.x + va0.y * vb0.y + va0.z * vb0.z + va0.w * vb0.w
                    + va1.x * vb1.x + va1.y * vb1.y + va1.z * vb1.z + va1.w * vb1.w;
            #pragma unroll
            for (int off = 16; off; off >>= 1)
                s += __shfl_down_sync(0xffffffffu, s, off);
            if (lane == 0) out[p] = s;
        }
    }
}

// ---------------- launch ----------------------------------------------------
extern "C" void kernel_launch(void* const* d_in, const int* in_sizes, int n_in,
                              void* d_out, int out_size) {
    const float* x     = (const float*)d_in[0];
    const int*   ddb   = (const int*)d_in[1];
    const int*   sg_ei = (const int*)d_in[4];
    const int*   nodes = (const int*)d_in[5];
    const int*   avgix = (const int*)d_in[6];
    const float* W1    = (const float*)d_in[7];
    const float* b1    = (const float*)d_in[8];
    const float* W2    = (const float*)d_in[9];
    const float* b2    = (const float*)d_in[10];
    float* out = (float*)d_out;

    const int smem_bytes = (64 * ASTR + 16 * 256) * (int)sizeof(float);  // 83968
    static bool attr_set = false;
    if (!attr_set) {
        cudaFuncSetAttribute(mega_kernel, cudaFuncAttributeMaxDynamicSharedMemorySize,
                             smem_bytes);
        attr_set = true;
    }

    mega_kernel<<<NB, NT, smem_bytes>>>(x, ddb, sg_ei, sg_ei + E_SG,
                                        nodes, avgix, W1, b1, W2, b2, out);
}

// round 5
// speedup vs baseline: 40.9029x; 1.4914x over previous
#include <cuda_runtime.h>

#define NP     19000
#define E_SG   1500000
#define N_SG   800000
#define ND     1024
#define B_DD   4096
#define NB     148
#define NT     512
#define CHUNK  129          // ceil(NP/NB)
#define ASTR   264          // A tile row stride (floats), 256 + 8 pad
#define NTILE  297          // ceil(19000/64)

// ---------------- persistent device state (no allocation allowed) -----------
__device__ float    g_h1[NP * 256];
__device__ float    g_h2[NP * 256];
__device__ float    g_dinv[NP];
__device__ int      g_deg[NP];           // zero at entry; re-zeroed each run
__device__ int      g_rowstart[NP + 1];
__device__ int      g_fill[NP];
__device__ int      g_csr_src[E_SG];
__device__ float    g_drug[ND * 256];
__device__ int      g_drug_start[ND + 1];
__device__ int      g_part[NB];
__device__ int      g_poff[NB];
__device__ int      g_tctr[2];           // work-stealing tile counters (layer 0/1)
__device__ unsigned g_cnt;               // barrier arrival counter (self-resetting)
__device__ unsigned g_gen;               // barrier generation (monotone forever)

// Software grid barrier; all 148 blocks co-resident (148 SMs, 84KB smem, <=128 regs).
__device__ __forceinline__ void gridbar(unsigned gen0, unsigned k) {
    __syncthreads();
    if (threadIdx.x == 0) {
        __threadfence();
        unsigned pos = atomicAdd(&g_cnt, 1u);
        if (pos == NB - 1u) {
            atomicExch(&g_cnt, 0u);
            __threadfence();
            atomicAdd(&g_gen, 1u);
        } else {
            unsigned target = gen0 + k;
            while ((int)(*(volatile unsigned*)&g_gen - target) < 0) __nanosleep(64);
        }
        __threadfence();
    }
    __syncthreads();
}

// ---------------- fused GCN layer: agg (warp-per-row) + GEMM in smem --------
// Column mapping per lane: block0 = cols [lane*4, +4), block1 = cols [128+lane*4, +4)
__device__ void layer_phase(const float4* __restrict__ in, const float* __restrict__ W,
                            const float* __restrict__ bias, const float4* __restrict__ resid,
                            float4* __restrict__ out, bool relu, int layer,
                            float* A, float* Bs, int* s_tile) {
    const int tid  = threadIdx.x;
    const int lane = tid & 31;
    const int wid  = tid >> 5;           // 0..15

    for (;;) {
        __syncthreads();
        if (tid == 0) *s_tile = atomicAdd(&g_tctr[layer], 1);
        __syncthreads();
        const int tile = *s_tile;
        if (tile >= NTILE) break;
        const int r0 = tile * 64;

        // ---- gather: warp wid produces rows wid*4 .. wid*4+3 ----
        for (int i = 0; i < 4; i++) {
            int rr = wid * 4 + i;
            int r  = r0 + rr;
            float4 a0 = make_float4(0.f, 0.f, 0.f, 0.f);
            float4 a1 = make_float4(0.f, 0.f, 0.f, 0.f);
            if (r < NP) {
                int beg = g_rowstart[r];
                int end = g_rowstart[r + 1];
                for (int base = beg; base < end; base += 32) {
                    int m = min(32, end - base);
                    int sidx = 0; float sw = 0.f;
                    if (lane < m) {
                        int s = g_csr_src[base + lane];
                        sidx = s * 64;
                        sw   = g_dinv[s];
                    }
                    int k = 0;
                    for (; k + 2 <= m; k += 2) {
                        int   i0 = __shfl_sync(0xffffffffu, sidx, k);
                        float w0 = __shfl_sync(0xffffffffu, sw,   k);
                        int   i1 = __shfl_sync(0xffffffffu, sidx, k + 1);
                        float w1 = __shfl_sync(0xffffffffu, sw,   k + 1);
                        float4 p0 = in[i0 + lane];
                        float4 p1 = in[i0 + 32 + lane];
                        float4 q0 = in[i1 + lane];
                        float4 q1 = in[i1 + 32 + lane];
                        a0.x = fmaf(p0.x, w0, a0.x); a0.y = fmaf(p0.y, w0, a0.y);
                        a0.z = fmaf(p0.z, w0, a0.z); a0.w = fmaf(p0.w, w0, a0.w);
                        a1.x = fmaf(p1.x, w0, a1.x); a1.y = fmaf(p1.y, w0, a1.y);
                        a1.z = fmaf(p1.z, w0, a1.z); a1.w = fmaf(p1.w, w0, a1.w);
                        a0.x = fmaf(q0.x, w1, a0.x); a0.y = fmaf(q0.y, w1, a0.y);
                        a0.z = fmaf(q0.z, w1, a0.z); a0.w = fmaf(q0.w, w1, a0.w);
                        a1.x = fmaf(q1.x, w1, a1.x); a1.y = fmaf(q1.y, w1, a1.y);
                        a1.z = fmaf(q1.z, w1, a1.z); a1.w = fmaf(q1.w, w1, a1.w);
                    }
                    if (k < m) {
                        int   i0 = __shfl_sync(0xffffffffu, sidx, k);
                        float w0 = __shfl_sync(0xffffffffu, sw,   k);
                        float4 p0 = in[i0 + lane];
                        float4 p1 = in[i0 + 32 + lane];
                        a0.x = fmaf(p0.x, w0, a0.x); a0.y = fmaf(p0.y, w0, a0.y);
                        a0.z = fmaf(p0.z, w0, a0.z); a0.w = fmaf(p0.w, w0, a0.w);
                        a1.x = fmaf(p1.x, w0, a1.x); a1.y = fmaf(p1.y, w0, a1.y);
                        a1.z = fmaf(p1.z, w0, a1.z); a1.w = fmaf(p1.w, w0, a1.w);
                    }
                }
                float di = g_dinv[r];
                float4 s0 = in[r * 64 + lane];
                float4 s1 = in[r * 64 + 32 + lane];
                a0.x = (a0.x + s0.x * di) * di; a0.y = (a0.y + s0.y * di) * di;
                a0.z = (a0.z + s0.z * di) * di; a0.w = (a0.w + s0.w * di) * di;
                a1.x = (a1.x + s1.x * di) * di; a1.y = (a1.y + s1.y * di) * di;
                a1.z = (a1.z + s1.z * di) * di; a1.w = (a1.w + s1.w * di) * di;
            }
            *(float4*)&A[rr * ASTR + lane * 4]       = a0;
            *(float4*)&A[rr * ASTR + 128 + lane * 4] = a1;
        }
        __syncthreads();

        // ---- GEMM: H[64,256] = A[64,256] * W[256,256] ----
        float acc[4][8];
        #pragma unroll
        for (int i = 0; i < 4; i++)
            #pragma unroll
            for (int j = 0; j < 8; j++) acc[i][j] = 0.f;

        for (int k0 = 0; k0 < 256; k0 += 16) {
            #pragma unroll
            for (int q = 0; q < 2; q++) {
                int l  = tid + 512 * q;      // 0..1023
                int br = l >> 6;             // 0..15
                int bc = (l & 63) * 4;       // 0..252
                *(float4*)&Bs[br * 256 + bc] = *(const float4*)&W[(k0 + br) * 256 + bc];
            }
            __syncthreads();
            #pragma unroll
            for (int k = 0; k < 16; k++) {
                float a[4];
                #pragma unroll
                for (int i = 0; i < 4; i++) a[i] = A[(wid * 4 + i) * ASTR + k0 + k];
                float4 b0 = *(float4*)&Bs[k * 256 + lane * 4];
                float4 b1 = *(float4*)&Bs[k * 256 + 128 + lane * 4];
                #pragma unroll
                for (int i = 0; i < 4; i++) {
                    acc[i][0] = fmaf(a[i], b0.x, acc[i][0]);
                    acc[i][1] = fmaf(a[i], b0.y, acc[i][1]);
                    acc[i][2] = fmaf(a[i], b0.z, acc[i][2]);
                    acc[i][3] = fmaf(a[i], b0.w, acc[i][3]);
                    acc[i][4] = fmaf(a[i], b1.x, acc[i][4]);
                    acc[i][5] = fmaf(a[i], b1.y, acc[i][5]);
                    acc[i][6] = fmaf(a[i], b1.z, acc[i][6]);
                    acc[i][7] = fmaf(a[i], b1.w, acc[i][7]);
                }
            }
            __syncthreads();
        }

        // ---- epilogue: bias (+residual) (+relu) -> out ----
        float4 bi0 = *(const float4*)&bias[lane * 4];
        float4 bi1 = *(const float4*)&bias[128 + lane * 4];
        #pragma unroll
        for (int i = 0; i < 4; i++) {
            int r = r0 + wid * 4 + i;
            if (r < NP) {
                float4 o0 = make_float4(acc[i][0] + bi0.x, acc[i][1] + bi0.y,
                                        acc[i][2] + bi0.z, acc[i][3] + bi0.w);
                float4 o1 = make_float4(acc[i][4] + bi1.x, acc[i][5] + bi1.y,
                                        acc[i][6] + bi1.z, acc[i][7] + bi1.w);
                if (resid) {
                    float4 r4 = resid[r * 64 + lane];
                    float4 r5 = resid[r * 64 + 32 + lane];
                    o0.x += r4.x; o0.y += r4.y; o0.z += r4.z; o0.w += r4.w;
                    o1.x += r5.x; o1.y += r5.y; o1.z += r5.z; o1.w += r5.w;
                }
                if (relu) {
                    o0.x = fmaxf(o0.x, 0.f); o0.y = fmaxf(o0.y, 0.f);
                    o0.z = fmaxf(o0.z, 0.f); o0.w = fmaxf(o0.w, 0.f);
                    o1.x = fmaxf(o1.x, 0.f); o1.y = fmaxf(o1.y, 0.f);
                    o1.z = fmaxf(o1.z, 0.f); o1.w = fmaxf(o1.w, 0.f);
                }
                out[r * 64 + lane]      = o0;
                out[r * 64 + 32 + lane] = o1;
            }
        }
    }
}

// ---------------- the single mega-kernel ------------------------------------
__global__ __launch_bounds__(NT) void mega_kernel(
    const float* __restrict__ x, const int* __restrict__ ddb,
    const int* __restrict__ src, const int* __restrict__ dst,
    const int* __restrict__ nodes, const int* __restrict__ avgix,
    const float* __restrict__ W1, const float* __restrict__ b1,
    const float* __restrict__ W2, const float* __restrict__ b2,
    float* __restrict__ out)
{
    extern __shared__ float smem[];
    float* A  = smem;                  // 64 * 264 floats
    float* Bs = smem + 64 * ASTR;      // 16 * 256 floats
    __shared__ unsigned s_gen0;
    __shared__ int s_tile;

    const int tid  = threadIdx.x;
    const int lane = tid & 31;
    const int wid  = tid >> 5;
    const int gtid = blockIdx.x * NT + tid;
    const int gs   = NB * NT;

    if (tid == 0) s_gen0 = *(volatile unsigned*)&g_gen;
    __syncthreads();
    const unsigned gen0 = s_gen0;

    // ---- P0: degree histogram + drug boundaries + counter reset ----
    for (int e = gtid; e < E_SG; e += gs)
        atomicAdd(&g_deg[dst[e]], 1);
    if (gtid < 2) g_tctr[gtid] = 0;
    if (gtid <= ND) {
        if (gtid == ND) g_drug_start[ND] = N_SG;
        else {
            int lo = 0, hi = N_SG;
            while (lo < hi) {
                int mid = (lo + hi) >> 1;
                if (avgix[mid] < gtid) lo = mid + 1; else hi = mid;
            }
            g_drug_start[gtid] = lo;
        }
    }
    gridbar(gen0, 1);

    // ---- P1a: per-block chunk sums ----
    int* si = (int*)A;
    {
        int n0  = blockIdx.x * CHUNK;
        int len = NP - n0; if (len > CHUNK) len = CHUNK; if (len < 0) len = 0;
        int v = (tid < len) ? g_deg[n0 + tid] : 0;
        si[tid] = v;
        __syncthreads();
        if (tid == 0) {
            int s = 0;
            for (int i = 0; i < len; i++) s += si[i];
            g_part[blockIdx.x] = s;
        }
    }
    gridbar(gen0, 2);

    // ---- P1b: block 0 scans the 148 partials ----
    if (blockIdx.x == 0) {
        int pv = (tid < NB) ? g_part[tid] : 0;
        si[tid] = pv;
        __syncthreads();
        if (tid == 0) {
            int run = 0;
            for (int i = 0; i < NB; i++) { int t = si[i]; si[i] = run; run += t; }
        }
        __syncthreads();
        if (tid < NB) g_poff[tid] = si[tid];
    }
    gridbar(gen0, 3);

    // ---- P1c: per-chunk prefix -> rowstart/fill/dinv ----
    {
        int n0  = blockIdx.x * CHUNK;
        int len = NP - n0; if (len > CHUNK) len = CHUNK; if (len < 0) len = 0;
        int v = (tid < len) ? g_deg[n0 + tid] : 0;
        si[tid] = v;
        __syncthreads();
        if (tid == 0) {
            int run = g_poff[blockIdx.x];
            for (int i = 0; i < len; i++) { int t = si[i]; si[i] = run; run += t; }
        }
        __syncthreads();
        if (tid < len) {
            int node = n0 + tid;
            int rs = si[tid];
            g_rowstart[node] = rs;
            g_fill[node]     = rs;
            g_dinv[node]     = rsqrtf((float)v + 1.0f);
        }
        if (blockIdx.x == 0 && tid == 0) g_rowstart[NP] = E_SG;
    }
    gridbar(gen0, 4);

    // ---- P2: CSR fill + reset g_deg for next replay ----
    for (int e = gtid; e < E_SG; e += gs) {
        int d   = dst[e];
        int pos = atomicAdd(&g_fill[d], 1);
        g_csr_src[pos] = src[e];
    }
    for (int i = gtid; i < NP; i += gs) g_deg[i] = 0;
    gridbar(gen0, 5);

    // ---- P3: layer 1  h1 = relu(agg(x) @ W1 + b1) ----
    layer_phase((const float4*)x, W1, b1, nullptr, (float4*)g_h1, true, 0, A, Bs, &s_tile);
    gridbar(gen0, 6);

    // ---- P4: layer 2  h2 = agg(h1) @ W2 + b2 + h1 ----
    layer_phase((const float4*)g_h1, W2, b2, (const float4*)g_h1, (float4*)g_h2, false, 1,
                A, Bs, &s_tile);
    gridbar(gen0, 7);

    // ---- P5: scatter-mean pooling (16 warps gather, smem reduce) ----
    {
        const float4* h2 = (const float4*)g_h2;
        for (int d = blockIdx.x; d < ND; d += NB) {
            int beg = g_drug_start[d];
            int end = g_drug_start[d + 1];
            float4 a0 = make_float4(0.f, 0.f, 0.f, 0.f);
            float4 a1 = make_float4(0.f, 0.f, 0.f, 0.f);
            for (int base = beg + wid * 32; base < end; base += NT) {
                int m = min(32, end - base);
                int nidx = 0;
                if (lane < m) nidx = nodes[base + lane] * 64;
                int k = 0;
                for (; k + 2 <= m; k += 2) {
                    int i0 = __shfl_sync(0xffffffffu, nidx, k);
                    int i1 = __shfl_sync(0xffffffffu, nidx, k + 1);
                    float4 p0 = h2[i0 + lane];
                    float4 p1 = h2[i0 + 32 + lane];
                    float4 q0 = h2[i1 + lane];
                    float4 q1 = h2[i1 + 32 + lane];
                    a0.x += p0.x + q0.x; a0.y += p0.y + q0.y;
                    a0.z += p0.z + q0.z; a0.w += p0.w + q0.w;
                    a1.x += p1.x + q1.x; a1.y += p1.y + q1.y;
                    a1.z += p1.z + q1.z; a1.w += p1.w + q1.w;
                }
                if (k < m) {
                    int i0 = __shfl_sync(0xffffffffu, nidx, k);
                    float4 p0 = h2[i0 + lane];
                    float4 p1 = h2[i0 + 32 + lane];
                    a0.x += p0.x; a0.y += p0.y; a0.z += p0.z; a0.w += p0.w;
                    a1.x += p1.x; a1.y += p1.y; a1.z += p1.z; a1.w += p1.w;
                }
            }
            __syncthreads();
            float* P = A;   // 16 warps x 256 floats
            *(float4*)&P[wid * 256 + lane * 4]       = a0;
            *(float4*)&P[wid * 256 + 128 + lane * 4] = a1;
            __syncthreads();
            if (tid < 256) {
                float s = 0.f;
                #pragma unroll
                for (int w = 0; w < 16; w++) s += P[w * 256 + tid];
                float inv = 1.0f / fmaxf((float)(end - beg), 1.0f);
                g_drug[d * 256 + tid] = s * inv;
            }
            __syncthreads();
        }
    }
    gridbar(gen0, 8);

    // ---- P6: prediction head ----
    {
        const float4* gd = (const float4*)g_drug;
        for (int p = blockIdx.x * 16 + wid; p < B_DD; p += NB * 16) {
            int a = ddb[p];
            int b = ddb[B_DD + p];
            float4 va0 = gd[a * 64 + lane], va1 = gd[a * 64 + 32 + lane];
            float4 vb0 = gd[b * 64 + lane], vb1 = gd[b * 64 + 32 + lane];
            float s = va0.x * vb0.x + va0.y * vb0.y + va0.z * vb0.z + va0.w * vb0.w
                    + va1.x * vb1.x + va1.y * vb1.y + va1.z * vb1.z + va1.w * vb1.w;
            #pragma unroll
            for (int off = 16; off; off >>= 1)
                s += __shfl_down_sync(0xffffffffu, s, off);
            if (lane == 0) out[p] = s;
        }
    }
}

// ---------------- launch ----------------------------------------------------
extern "C" void kernel_launch(void* const* d_in, const int* in_sizes, int n_in,
                              void* d_out, int out_size) {
    const float* x     = (const float*)d_in[0];
    const int*   ddb   = (const int*)d_in[1];
    const int*   sg_ei = (const int*)d_in[4];
    const int*   nodes = (const int*)d_in[5];
    const int*   avgix = (const int*)d_in[6];
    const float* W1    = (const float*)d_in[7];
    const float* b1    = (const float*)d_in[8];
    const float* W2    = (const float*)d_in[9];
    const float* b2    = (const float*)d_in[10];
    float* out = (float*)d_out;

    const int smem_bytes = (64 * ASTR + 16 * 256) * (int)sizeof(float);  // 83968
    static bool attr_set = false;
    if (!attr_set) {
        cudaFuncSetAttribute(mega_kernel, cudaFuncAttributeMaxDynamicSharedMemorySize,
                             smem_bytes);
        attr_set = true;
    }

    mega_kernel<<<NB, NT, smem_bytes>>>(x, ddb, sg_ei, sg_ei + E_SG,
                                        nodes, avgix, W1, b1, W2, b2, out);
}